// round 17
// baseline (speedup 1.0000x reference)
#include <cuda_runtime.h>
#include <cstdint>

// AggrSum: out[n, :] = sum over edges e with X_node[e] == n of H[e, :]
// H: [2M, 32] f32, X_node: [2M] i32 (harness downcast), out: [100K, 32] f32
//
// R17 (final): best-measured config (R16) with 512-thread scatter blocks
// (halves CTA count; identical per-thread code, regs, occupancy profile).
//  - cudaMemsetAsync graph node for zeroing (measured cheapest: 2.3us).
//  - UNROLL=4 front-batched RED.v4 scatter, exact cover, evict-first streams.
//
// Why this is the floor (measured R2-R16):
//  - red.v4.f32 is HW-max width (ptxas rejects .v8) -> 16M atomic ops
//    irreducible; scatter pinned at 56.9-57.2us across occ 42-85%,
//    MLP 2-8, LDG-vs-TMA, L2 policies -> L2 RMW slice-cycle wall.
//  - CSR gather (62.7us + ~20us build), TMA staging (63.4us), and
//    accumulator+finalize (8.2us epilogue) all measured and rejected.

static constexpr int D = 32;
static constexpr int VEC = 4;
static constexpr int LANES = D / VEC;   // 8 float4s per edge row
static constexpr int UNROLL = 4;
static constexpr int THREADS = 512;

__device__ __forceinline__ void red_add_v4(float* dst, float4 v) {
    asm volatile("red.global.add.v4.f32 [%0], {%1, %2, %3, %4};"
                 :: "l"(dst), "f"(v.x), "f"(v.y), "f"(v.z), "f"(v.w)
                 : "memory");
}

__global__ void __launch_bounds__(THREADS, 3)
scatter_add_kernel(const float4* __restrict__ H,
                   const int* __restrict__ idx,
                   float* __restrict__ out,
                   int nitems, int node_num) {
    const int T = gridDim.x * blockDim.x;   // stride between a thread's items
    const int t = blockIdx.x * blockDim.x + threadIdx.x;

    if (t + 3 * T < nitems) {
        // Fast path (always taken at the bench shape): 4 independent
        // LDG.128 + 4 broadcast idx loads front-batched, then 4 REDs.
        float4 v0 = __ldcs(&H[t]);
        float4 v1 = __ldcs(&H[t + T]);
        float4 v2 = __ldcs(&H[t + 2 * T]);
        float4 v3 = __ldcs(&H[t + 3 * T]);
        int n0 = __ldcs(&idx[t >> 3]);
        int n1 = __ldcs(&idx[(t + T) >> 3]);
        int n2 = __ldcs(&idx[(t + 2 * T) >> 3]);
        int n3 = __ldcs(&idx[(t + 3 * T) >> 3]);

        if ((unsigned)n0 < (unsigned)node_num)
            red_add_v4(out + (size_t)(unsigned)n0 * D + (t & (LANES - 1)) * VEC, v0);
        if ((unsigned)n1 < (unsigned)node_num)
            red_add_v4(out + (size_t)(unsigned)n1 * D + ((t + T) & (LANES - 1)) * VEC, v1);
        if ((unsigned)n2 < (unsigned)node_num)
            red_add_v4(out + (size_t)(unsigned)n2 * D + ((t + 2 * T) & (LANES - 1)) * VEC, v2);
        if ((unsigned)n3 < (unsigned)node_num)
            red_add_v4(out + (size_t)(unsigned)n3 * D + ((t + 3 * T) & (LANES - 1)) * VEC, v3);
    } else {
        // Tail (not taken when nitems % (T*UNROLL) == 0).
        #pragma unroll
        for (int k = 0; k < UNROLL; k++) {
            int i = t + k * T;
            if (i < nitems) {
                float4 v = __ldcs(&H[i]);
                int n = __ldcs(&idx[i >> 3]);
                if ((unsigned)n < (unsigned)node_num)
                    red_add_v4(out + (size_t)(unsigned)n * D + (i & (LANES - 1)) * VEC, v);
            }
        }
    }
}

extern "C" void kernel_launch(void* const* d_in, const int* in_sizes, int n_in,
                              void* d_out, int out_size) {
    const float4* H = (const float4*)d_in[0];
    const int* idx = (const int*)d_in[1];
    float* out = (float*)d_out;

    int num_edges = in_sizes[0] / D;
    int node_num = out_size / D;
    int nitems = num_edges * LANES;   // 16M float4 items at the bench shape

    // 1) zero output (poisoned to 0xAA): graph memset node.
    cudaMemsetAsync(d_out, 0, (size_t)out_size * sizeof(float));

    // 2) scatter-add: exact cover, one 4-item batch per thread.
    {
        long long want = ((long long)nitems + UNROLL - 1) / UNROLL;
        int blocks = (int)((want + THREADS - 1) / THREADS);
        scatter_add_kernel<<<blocks, THREADS>>>(H, idx, out, nitems, node_num);
    }
}